// round 10
// baseline (speedup 1.0000x reference)
#include <cuda_runtime.h>
#include <cuda_bf16.h>
#include <cstdint>
#include <math.h>

// ---------------- problem constants ----------------
#define NB    8
#define CIN   64
#define OO    128
#define KKK   9
#define KDIM  576          // CIN * 9
#define NOFF  1152         // 2 * CIN * 9
#define NTOT  1728         // offset + mask channels
#define MTOT  32768        // NB * H * W
#define MAXOFF 16.0f

// ---------------- scratch (device globals, allocation-free) ----------------
__device__ __align__(16) __nv_bfloat16 g_colh[(size_t)MTOT * KDIM];  // im2col hi [m][k]
__device__ __align__(16) __nv_bfloat16 g_coll[(size_t)MTOT * KDIM];  // im2col lo [m][k]
__device__ __align__(16) __nv_bfloat16 g_wh  [(size_t)NTOT * KDIM];  // conv weights hi [n][k]
__device__ __align__(16) __nv_bfloat16 g_wl  [(size_t)NTOT * KDIM];  // conv weights lo [n][k]
__device__ __align__(16) __nv_bfloat16 g_wch [OO * KDIM];            // w_conv hi [o][j]
__device__ __align__(16) __nv_bfloat16 g_wcl [OO * KDIM];            // w_conv lo [o][j]
__device__ float g_bias[NTOT];
__device__ float g_off [(size_t)NOFF * MTOT];            // offsets [n][m]
__device__ float g_mask[(size_t)(NTOT - NOFF) * MTOT];   // mask    [n][m]

// ---------------- PTX helpers (baseline sm_80+ features only) ----------------
__device__ __forceinline__ uint32_t smem_u32(const void* p) {
    uint32_t a;
    asm("{ .reg .u64 t; cvta.to.shared.u64 t, %1; cvt.u32.u64 %0, t; }" : "=r"(a) : "l"(p));
    return a;
}
__device__ __forceinline__ void cp_async16(uint32_t dst, const void* src) {
    asm volatile("cp.async.cg.shared.global [%0], [%1], 16;" :: "r"(dst), "l"(src));
}
__device__ __forceinline__ void sts32(uint32_t addr, uint32_t v) {
    asm volatile("st.shared.b32 [%0], %1;" :: "r"(addr), "r"(v) : "memory");
}
__device__ __forceinline__ void ldsm_x4(uint32_t& r0, uint32_t& r1, uint32_t& r2, uint32_t& r3,
                                        uint32_t addr) {
    asm volatile("ldmatrix.sync.aligned.m8n8.x4.shared.b16 {%0,%1,%2,%3}, [%4];"
                 : "=r"(r0), "=r"(r1), "=r"(r2), "=r"(r3) : "r"(addr));
}
__device__ __forceinline__ void ldsm_x4t(uint32_t& r0, uint32_t& r1, uint32_t& r2, uint32_t& r3,
                                         uint32_t addr) {
    asm volatile("ldmatrix.sync.aligned.m8n8.x4.trans.shared.b16 {%0,%1,%2,%3}, [%4];"
                 : "=r"(r0), "=r"(r1), "=r"(r2), "=r"(r3) : "r"(addr));
}
__device__ __forceinline__ void mma16816(float* d, const uint32_t* a, const uint32_t* b) {
    asm volatile(
        "mma.sync.aligned.m16n8k16.row.col.f32.bf16.bf16.f32 "
        "{%0,%1,%2,%3}, {%4,%5,%6,%7}, {%8,%9}, {%0,%1,%2,%3};"
        : "+f"(d[0]), "+f"(d[1]), "+f"(d[2]), "+f"(d[3])
        : "r"(a[0]), "r"(a[1]), "r"(a[2]), "r"(a[3]), "r"(b[0]), "r"(b[1]));
}

// ---------------- kernel 1: im2col -> bf16 hi/lo in [m][k] layout ----------------
__global__ __launch_bounds__(576) void im2col_bf16_k(const float* __restrict__ x) {
    const int m = blockIdx.x;
    const int k = threadIdx.x;          // 0..575
    const int w = m & 63, h = (m >> 6) & 63, b = m >> 12;
    const int c = k / KKK, kk = k - c * KKK;
    const int ki = kk / 3, kj = kk - ki * 3;
    const int ih = h + ki - 1, iw = w + kj - 1;
    float v = 0.f;
    if ((unsigned)ih < 64u && (unsigned)iw < 64u)
        v = x[(((b * CIN + c) << 6) + ih) * 64 + iw];
    __nv_bfloat16 hi = __float2bfloat16(v);
    __nv_bfloat16 lo = __float2bfloat16(v - __bfloat162float(hi));
    size_t idx = (size_t)m * KDIM + k;
    g_colh[idx] = hi;
    g_coll[idx] = lo;
}

// ---------------- kernel 2: conv weight split + bias merge ----------------
__global__ __launch_bounds__(576) void wprep_k(const float* __restrict__ w_off,
                                               const float* __restrict__ b_off,
                                               const float* __restrict__ w_mod,
                                               const float* __restrict__ b_mod) {
    const int n = blockIdx.x;           // 0..1727
    const int k = threadIdx.x;          // 0..575
    float v = (n < NOFF) ? w_off[(size_t)n * KDIM + k]
                         : w_mod[(size_t)(n - NOFF) * KDIM + k];
    __nv_bfloat16 hi = __float2bfloat16(v);
    __nv_bfloat16 lo = __float2bfloat16(v - __bfloat162float(hi));
    size_t idx = (size_t)n * KDIM + k;
    g_wh[idx] = hi;
    g_wl[idx] = lo;
    if (k == 0)
        g_bias[n] = (n < NOFF) ? b_off[n] : b_mod[n - NOFF];
}

// ---------------- kernel 2b: w_conv split [o][j] ----------------
__global__ __launch_bounds__(576) void wcprep_k(const float* __restrict__ w_conv) {
    int idx = blockIdx.x * 576 + threadIdx.x;     // 128 blocks x 576
    float v = w_conv[idx];
    __nv_bfloat16 hi = __float2bfloat16(v);
    __nv_bfloat16 lo = __float2bfloat16(v - __bfloat162float(hi));
    g_wch[idx] = hi;
    g_wcl[idx] = lo;
}

// ---------------- kernel 3: fused bf16x3 GEMM for offset+mask conv ----------------
// D[m][n] = sum_k col[m][k] * w[n][k].  Per 32-wide k-chunk the stage holds
// hi|lo interleaved per 128B row: chunks 0-3 = hi k[0:32], chunks 4-7 = lo.
#define BM 128
#define BN 96
#define BK 32
#define NSTAGE 3
#define A_STAGE (BM * 128)               // 16384 B (hi|lo per row)
#define B_STAGE (BN * 128)               // 12288 B
#define STAGE_B (A_STAGE + B_STAGE)      // 28672 B
#define GEMM_SMEM (NSTAGE * STAGE_B)     // 86016 B
#define VCHUNKS 18                       // 576/32

__device__ __forceinline__ int swz(int r, int c) { return c ^ (r & 7); }

__global__ void __launch_bounds__(256, 2) gemm_mma_k() {
    extern __shared__ char sm[];
    const int tid = threadIdx.x;
    const int wid = tid >> 5;
    const int lane = tid & 31;
    const int warp_m = wid & 3;
    const int warp_n = wid >> 2;
    const int m0 = blockIdx.x * BM;
    const int n0 = blockIdx.y * BN;
    const uint32_t smem_base = smem_u32(sm);

    float acc[2][6][4];
#pragma unroll
    for (int i = 0; i < 2; i++)
#pragma unroll
        for (int j = 0; j < 6; j++)
#pragma unroll
            for (int q = 0; q < 4; q++) acc[i][j][q] = 0.f;

    auto load_stage = [&](int s, int chunk) {
        const int k0 = chunk * BK;
        const uint32_t ab = smem_base + s * STAGE_B;
        const uint32_t bb = ab + A_STAGE;
#pragma unroll
        for (int i = 0; i < 4; i++) {          // A: 1024 chunks (hi: c<4, lo: c>=4)
            int e = tid + i * 256;
            int r = e >> 3, c = e & 7;
            const __nv_bfloat16* src = (c & 4) ? g_coll : g_colh;
            cp_async16(ab + r * 128 + swz(r, c) * 16,
                       src + (size_t)(m0 + r) * KDIM + k0 + (c & 3) * 8);
        }
#pragma unroll
        for (int i = 0; i < 3; i++) {          // B: 768 chunks
            int e = tid + i * 256;
            int r = e >> 3, c = e & 7;
            const __nv_bfloat16* src = (c & 4) ? g_wl : g_wh;
            cp_async16(bb + r * 128 + swz(r, c) * 16,
                       src + (size_t)(n0 + r) * KDIM + k0 + (c & 3) * 8);
        }
        asm volatile("cp.async.commit_group;");
    };

    load_stage(0, 0);
    load_stage(1, 1);

    for (int q = 0; q < VCHUNKS; q++) {
        asm volatile("cp.async.wait_group 1;");
        __syncthreads();
        if (q + 2 < VCHUNKS) load_stage((q + 2) % NSTAGE, q + 2);

        const uint32_t ab = smem_base + (q % NSTAGE) * STAGE_B;
        const uint32_t bb = ab + A_STAGE;
#pragma unroll
        for (int ks = 0; ks < 2; ks++) {       // 2 x k16 within BK=32
            uint32_t ah[2][4], al[2][4];
#pragma unroll
            for (int mf = 0; mf < 2; mf++) {
                int r = warp_m * 32 + mf * 16 + (lane & 15);
                int ch = ks * 2 + (lane >> 4);
                ldsm_x4(ah[mf][0], ah[mf][1], ah[mf][2], ah[mf][3],
                        ab + r * 128 + swz(r, ch) * 16);
                ldsm_x4(al[mf][0], al[mf][1], al[mf][2], al[mf][3],
                        ab + r * 128 + swz(r, ch + 4) * 16);
            }
#pragma unroll
            for (int nfp = 0; nfp < 3; nfp++) {
                int r = warp_n * 48 + nfp * 16 + (lane & 7) + ((lane >> 4) & 1) * 8;
                int ch = ks * 2 + ((lane >> 3) & 1);
                uint32_t bh[4], bl[4];
                ldsm_x4(bh[0], bh[1], bh[2], bh[3], bb + r * 128 + swz(r, ch) * 16);
                ldsm_x4(bl[0], bl[1], bl[2], bl[3], bb + r * 128 + swz(r, ch + 4) * 16);
                mma16816(acc[0][2 * nfp],     ah[0], bh);
                mma16816(acc[0][2 * nfp + 1], ah[0], bh + 2);
                mma16816(acc[1][2 * nfp],     ah[1], bh);
                mma16816(acc[1][2 * nfp + 1], ah[1], bh + 2);
                mma16816(acc[0][2 * nfp],     al[0], bh);
                mma16816(acc[0][2 * nfp + 1], al[0], bh + 2);
                mma16816(acc[1][2 * nfp],     al[1], bh);
                mma16816(acc[1][2 * nfp + 1], al[1], bh + 2);
                mma16816(acc[0][2 * nfp],     ah[0], bl);
                mma16816(acc[0][2 * nfp + 1], ah[0], bl + 2);
                mma16816(acc[1][2 * nfp],     ah[1], bl);
                mma16816(acc[1][2 * nfp + 1], ah[1], bl + 2);
            }
        }
    }
    __syncthreads();

    // epilogue: transpose via SMEM, coalesced [n][m] stores
    float* ws = (float*)sm + wid * (48 * 33);
#pragma unroll
    for (int mf = 0; mf < 2; mf++)
#pragma unroll
        for (int nf = 0; nf < 6; nf++)
#pragma unroll
            for (int j = 0; j < 4; j++) {
                int nl = (nf >> 1) * 16 + (nf & 1) * 8 + (lane & 3) * 2 + (j & 1);
                int ml = mf * 16 + ((j >> 1) & 1) * 8 + (lane >> 2);
                ws[nl * 33 + ml] = acc[mf][nf][j];
            }
    __syncwarp();
    {
        const int m = m0 + warp_m * 32 + lane;
#pragma unroll 4
        for (int row = 0; row < 48; row++) {
            int n = n0 + warp_n * 48 + row;
            float v = ws[row * 33 + lane] + g_bias[n];
            if (n < NOFF) {
                v = fminf(MAXOFF, fmaxf(-MAXOFF, v));
                g_off[(size_t)n * MTOT + m] = v;
            } else {
                g_mask[(size_t)(n - NOFF) * MTOT + m] = v;
            }
        }
    }
}

// ---------------- kernel 4: FUSED sampler + output GEMM ----------------
// out[o][m] = sum_j w_conv[o][j] * samp[j][m], samp computed in-kernel.
// CTA: 128 o x 128 m; 18 chunks of 32 j. A (weights) via 3-stage cp.async ring
// (hi|lo per 128B row). B (samples) computed by the CTA into a 3-slot SMEM ring:
// Bh 32x256B + Bl 32x256B per slot, swizzled for ldmatrix.trans.
#define FA_STAGE 16384                    // 128 rows x 128B
#define FA_RING  (3 * FA_STAGE)           // 49152
#define FB_STAGE 16384                    // Bh 8192 + Bl 8192
#define FB_RING  (3 * FB_STAGE)           // 49152
#define FUSED_SMEM (FA_RING + FB_RING)    // 98304

__global__ void __launch_bounds__(256, 2) fused_out_k(const float* __restrict__ x,
                                                      float* __restrict__ out) {
    extern __shared__ char sm[];
    const int tid = threadIdx.x;
    const int wid = tid >> 5;
    const int lane = tid & 31;
    const int warp_o = wid & 1;       // 2 warps x 64 o
    const int warp_n = wid >> 1;      // 4 warps x 32 m
    const int mm0 = blockIdx.x * 128;
    const uint32_t smem_base = smem_u32(sm);

    float acc[4][4][4];
#pragma unroll
    for (int i = 0; i < 4; i++)
#pragma unroll
        for (int j = 0; j < 4; j++)
#pragma unroll
            for (int q = 0; q < 4; q++) acc[i][j][q] = 0.f;

    // ---- A loader (weights, hi|lo per 128B row) ----
    auto loadA = [&](int chunk) {
        const int k0 = chunk * 32;
        const uint32_t ab = smem_base + (chunk % 3) * FA_STAGE;
#pragma unroll
        for (int i = 0; i < 4; i++) {          // 1024 16B chunks
            int e = tid + i * 256;
            int r = e >> 3, c = e & 7;
            const __nv_bfloat16* src = (c & 4) ? g_wcl : g_wch;
            cp_async16(ab + r * 128 + swz(r, c) * 16,
                       src + (size_t)r * KDIM + k0 + (c & 3) * 8);
        }
        asm volatile("cp.async.commit_group;");
    };

    // ---- B producer: compute 32j x 128m samples into ring slot ----
    const int m2 = (tid & 63) * 2;
    const int msmp = mm0 + m2;
    const int wpix = msmp & 63, hpix = (msmp >> 6) & 63, bpix = msmp >> 12;
    const float* xb = x + ((size_t)bpix * CIN << 12);

    auto computeB = [&](int chunk) {
        const int jbase = chunk * 32;
        const uint32_t bbase = smem_base + FA_RING + (chunk % 3) * FB_STAGE;
#pragma unroll
        for (int i = 0; i < 8; i++) {
            const int jl = (tid >> 6) + 4 * i;        // 0..31
            const int j = jbase + jl;
            const int c = j / 9, kk = j - c * 9;
            const int ki = kk / 3, kj = kk - ki * 3;
            const float* offp  = g_off + ((size_t)(c * 18 + kk * 2)) * MTOT + msmp;
            const float* offp2 = offp + MTOT;
            const float* mp    = g_mask + ((size_t)(c * 9 + kk)) * MTOT + msmp;
            const float* xp    = xb + ((size_t)c << 12);
            float s[2];
#pragma unroll
            for (int t = 0; t < 2; t++) {
                float dy = offp[t], dx = offp2[t], mv = mp[t];
                float py = dy + (float)(hpix + ki - 1);
                float px = dx + (float)(wpix + kj - 1 + t);
                float v = 0.f;
                if (py > -1.f && py < 64.f && px > -1.f && px < 64.f) {
                    float y0f = floorf(py), x0f = floorf(px);
                    float wy = py - y0f, wx = px - x0f;
                    int y0 = (int)y0f, x0 = (int)x0f;
                    float v00 = 0.f, v01 = 0.f, v10 = 0.f, v11 = 0.f;
                    bool yi0 = (unsigned)y0 < 64u;
                    bool yi1 = (unsigned)(y0 + 1) < 64u;
                    bool xi0 = (unsigned)x0 < 64u;
                    bool xi1 = (unsigned)(x0 + 1) < 64u;
                    if (yi0 && xi0) v00 = xp[(y0 << 6) + x0];
                    if (yi0 && xi1) v01 = xp[(y0 << 6) + x0 + 1];
                    if (yi1 && xi0) v10 = xp[((y0 + 1) << 6) + x0];
                    if (yi1 && xi1) v11 = xp[((y0 + 1) << 6) + x0 + 1];
                    v = (1.f - wy) * ((1.f - wx) * v00 + wx * v01) +
                        wy * ((1.f - wx) * v10 + wx * v11);
                }
                s[t] = v * mv;
            }
            __nv_bfloat16 h0 = __float2bfloat16(s[0]);
            __nv_bfloat16 h1 = __float2bfloat16(s[1]);
            __nv_bfloat16 l0 = __float2bfloat16(s[0] - __bfloat162float(h0));
            __nv_bfloat16 l1 = __float2bfloat16(s[1] - __bfloat162float(h1));
            uint32_t hp = (uint32_t)__bfloat16_as_ushort(h0) |
                          ((uint32_t)__bfloat16_as_ushort(h1) << 16);
            uint32_t lp = (uint32_t)__bfloat16_as_ushort(l0) |
                          ((uint32_t)__bfloat16_as_ushort(l1) << 16);
            uint32_t byteoff = (uint32_t)m2 * 2;            // 0..252
            uint32_t addr = bbase + jl * 256 +
                            ((((byteoff >> 4) ^ (jl & 15))) << 4) + (byteoff & 15);
            sts32(addr, hp);
            sts32(addr + 8192, lp);
        }
    };

    // ---- prologue ----
    loadA(0);
    loadA(1);
    computeB(0);

    for (int q = 0; q < 18; q++) {
        asm volatile("cp.async.wait_group 1;");   // A(q) landed
        if (q + 1 < 18) computeB(q + 1);
        __syncthreads();                           // B(q) visible; MMA(q-1) done everywhere
        if (q + 2 < 18) loadA(q + 2);              // safe: A slot (q-1) free

        const uint32_t ab = smem_base + (q % 3) * FA_STAGE;
        const uint32_t bhb = smem_base + FA_RING + (q % 3) * FB_STAGE;
        const uint32_t blb = bhb + 8192;
#pragma unroll
        for (int ks = 0; ks < 2; ks++) {
            uint32_t ah[4][4], al[4][4];
#pragma unroll
            for (int mf = 0; mf < 4; mf++) {
                int r = warp_o * 64 + mf * 16 + (lane & 15);
                int ch = ks * 2 + (lane >> 4);
                ldsm_x4(ah[mf][0], ah[mf][1], ah[mf][2], ah[mf][3],
                        ab + r * 128 + swz(r, ch) * 16);
                ldsm_x4(al[mf][0], al[mf][1], al[mf][2], al[mf][3],
                        ab + r * 128 + swz(r, ch + 4) * 16);
            }
#pragma unroll
            for (int np = 0; np < 2; np++) {
                int j = ks * 16 + (lane & 15);
                int cn = warp_n * 4 + np * 2 + (lane >> 4);
                uint32_t bh[4], bl[4];
                ldsm_x4t(bh[0], bh[1], bh[2], bh[3],
                         bhb + j * 256 + ((cn ^ (j & 15)) << 4));
                ldsm_x4t(bl[0], bl[1], bl[2], bl[3],
                         blb + j * 256 + ((cn ^ (j & 15)) << 4));
#pragma unroll
                for (int mf = 0; mf < 4; mf++) {
                    mma16816(acc[mf][np * 2],     ah[mf], bh);
                    mma16816(acc[mf][np * 2 + 1], ah[mf], bh + 2);
                    mma16816(acc[mf][np * 2],     al[mf], bh);
                    mma16816(acc[mf][np * 2 + 1], al[mf], bh + 2);
                    mma16816(acc[mf][np * 2],     ah[mf], bl);
                    mma16816(acc[mf][np * 2 + 1], ah[mf], bl + 2);
                }
            }
        }
    }

    // ---- epilogue: direct stores, out[b][o][h][w] ----
    const int bidx = mm0 >> 12;
    const int rem0 = mm0 & 4095;
#pragma unroll
    for (int mf = 0; mf < 4; mf++) {
#pragma unroll
        for (int nf = 0; nf < 4; nf++) {
            int o = warp_o * 64 + mf * 16 + (lane >> 2);
            int mc = rem0 + warp_n * 32 + nf * 8 + (lane & 3) * 2;
            float* p0 = out + ((size_t)(bidx * OO + o) << 12) + mc;
            p0[0] = acc[mf][nf][0];
            p0[1] = acc[mf][nf][1];
            float* p1 = p0 + (8 << 12);
            p1[0] = acc[mf][nf][2];
            p1[1] = acc[mf][nf][3];
        }
    }
}

// ---------------- launch ----------------
extern "C" void kernel_launch(void* const* d_in, const int* in_sizes, int n_in,
                              void* d_out, int out_size) {
    const float* x      = (const float*)d_in[0];
    const float* w_off  = (const float*)d_in[1];
    const float* b_off  = (const float*)d_in[2];
    const float* w_mod  = (const float*)d_in[3];
    const float* b_mod  = (const float*)d_in[4];
    const float* w_conv = (const float*)d_in[5];
    float* out = (float*)d_out;

    static int smem_set = 0;
    if (!smem_set) {
        cudaFuncSetAttribute(gemm_mma_k, cudaFuncAttributeMaxDynamicSharedMemorySize, GEMM_SMEM);
        cudaFuncSetAttribute(fused_out_k, cudaFuncAttributeMaxDynamicSharedMemorySize, FUSED_SMEM);
        smem_set = 1;
    }

    im2col_bf16_k<<<MTOT, 576>>>(x);
    wprep_k<<<NTOT, 576>>>(w_off, b_off, w_mod, b_mod);
    wcprep_k<<<OO, 576>>>(w_conv);
    gemm_mma_k<<<dim3(MTOT / BM, NTOT / BN), 256, GEMM_SMEM>>>();
    fused_out_k<<<MTOT / 128, 256, FUSED_SMEM>>>(x, out);
}

// round 14
// speedup vs baseline: 1.0958x; 1.0958x over previous
#include <cuda_runtime.h>
#include <cuda_bf16.h>
#include <cstdint>
#include <math.h>

// ---------------- problem constants ----------------
#define NB    8
#define CIN   64
#define OO    128
#define KKK   9
#define KDIM  576          // CIN * 9
#define NOFF  1152         // 2 * CIN * 9
#define NTOT  1728         // offset + mask channels
#define MTOT  32768        // NB * H * W
#define MAXOFF 16.0f

// ---------------- scratch (device globals, allocation-free) ----------------
__device__ __align__(16) __nv_bfloat16 g_xth[(size_t)MTOT * CIN];    // x NHWC hi [m][c]
__device__ __align__(16) __nv_bfloat16 g_xtl[(size_t)MTOT * CIN];    // x NHWC lo [m][c]
__device__ __align__(16) __nv_bfloat16 g_wh [(size_t)NTOT * KDIM];   // weights hi [n][kk*64+c]
__device__ __align__(16) __nv_bfloat16 g_wl [(size_t)NTOT * KDIM];   // weights lo [n][kk*64+c]
__device__ __align__(16) __nv_bfloat16 g_wch[OO * KDIM];             // w_conv hi [o][c*9+kk]
__device__ __align__(16) __nv_bfloat16 g_wcl[OO * KDIM];             // w_conv lo [o][c*9+kk]
__device__ float g_bias[NTOT];
__device__ float g_off [(size_t)NOFF * MTOT];            // offsets [n][m]
__device__ float g_mask[(size_t)(NTOT - NOFF) * MTOT];   // mask    [n][m]

// ---------------- PTX helpers (baseline sm_80+ features only) ----------------
__device__ __forceinline__ uint32_t smem_u32(const void* p) {
    uint32_t a;
    asm("{ .reg .u64 t; cvta.to.shared.u64 t, %1; cvt.u32.u64 %0, t; }" : "=r"(a) : "l"(p));
    return a;
}
__device__ __forceinline__ void cp_async16(uint32_t dst, const void* src) {
    asm volatile("cp.async.cg.shared.global [%0], [%1], 16;" :: "r"(dst), "l"(src));
}
// zero-fill variant: srcsize==0 -> whole 16B zero-filled
__device__ __forceinline__ void cp_async16_z(uint32_t dst, const void* src, uint32_t srcsize) {
    asm volatile("cp.async.cg.shared.global [%0], [%1], 16, %2;"
                 :: "r"(dst), "l"(src), "r"(srcsize));
}
__device__ __forceinline__ void sts32(uint32_t addr, uint32_t v) {
    asm volatile("st.shared.b32 [%0], %1;" :: "r"(addr), "r"(v) : "memory");
}
__device__ __forceinline__ void ldsm_x4(uint32_t& r0, uint32_t& r1, uint32_t& r2, uint32_t& r3,
                                        uint32_t addr) {
    asm volatile("ldmatrix.sync.aligned.m8n8.x4.shared.b16 {%0,%1,%2,%3}, [%4];"
                 : "=r"(r0), "=r"(r1), "=r"(r2), "=r"(r3) : "r"(addr));
}
__device__ __forceinline__ void ldsm_x4t(uint32_t& r0, uint32_t& r1, uint32_t& r2, uint32_t& r3,
                                         uint32_t addr) {
    asm volatile("ldmatrix.sync.aligned.m8n8.x4.trans.shared.b16 {%0,%1,%2,%3}, [%4];"
                 : "=r"(r0), "=r"(r1), "=r"(r2), "=r"(r3) : "r"(addr));
}
__device__ __forceinline__ void mma16816(float* d, const uint32_t* a, const uint32_t* b) {
    asm volatile(
        "mma.sync.aligned.m16n8k16.row.col.f32.bf16.bf16.f32 "
        "{%0,%1,%2,%3}, {%4,%5,%6,%7}, {%8,%9}, {%0,%1,%2,%3};"
        : "+f"(d[0]), "+f"(d[1]), "+f"(d[2]), "+f"(d[3])
        : "r"(a[0]), "r"(a[1]), "r"(a[2]), "r"(a[3]), "r"(b[0]), "r"(b[1]));
}

// ---------------- kernel 1: x NCHW fp32 -> NHWC bf16 hi/lo (SMEM transpose) ----------------
// One block per (b,h) row: 64 w x 64 c.
__global__ __launch_bounds__(256) void xt_prep_k(const float* __restrict__ x) {
    __shared__ float tile[64][65];
    const int blk = blockIdx.x;             // 0..511
    const int b = blk >> 6, h = blk & 63;
    const int m0 = blk << 6;
    const int tx = threadIdx.x & 63;        // w (load) / c (store)
    const int ty = threadIdx.x >> 6;        // 0..3

#pragma unroll
    for (int i = 0; i < 16; i++) {
        int c = ty * 16 + i;
        tile[c][tx] = x[(((size_t)(b * CIN + c)) << 12) + (h << 6) + tx];
    }
    __syncthreads();
#pragma unroll
    for (int i = 0; i < 16; i++) {
        int w = ty * 16 + i;
        float v = tile[tx][w];
        __nv_bfloat16 hi = __float2bfloat16(v);
        __nv_bfloat16 lo = __float2bfloat16(v - __bfloat162float(hi));
        size_t idx = (size_t)(m0 + w) * CIN + tx;
        g_xth[idx] = hi;
        g_xtl[idx] = lo;
    }
}

// ---------------- kernel 2: conv weight split + bias merge; K reorder to kk*64+c ----------------
__global__ __launch_bounds__(576) void wprep_k(const float* __restrict__ w_off,
                                               const float* __restrict__ b_off,
                                               const float* __restrict__ w_mod,
                                               const float* __restrict__ b_mod) {
    const int n = blockIdx.x;           // 0..1727
    const int k = threadIdx.x;          // source index: c*9 + kk
    const int c = k / KKK, kk = k - c * KKK;
    float v = (n < NOFF) ? w_off[(size_t)n * KDIM + k]
                         : w_mod[(size_t)(n - NOFF) * KDIM + k];
    __nv_bfloat16 hi = __float2bfloat16(v);
    __nv_bfloat16 lo = __float2bfloat16(v - __bfloat162float(hi));
    size_t idx = (size_t)n * KDIM + kk * CIN + c;     // dest: kk*64 + c
    g_wh[idx] = hi;
    g_wl[idx] = lo;
    if (k == 0)
        g_bias[n] = (n < NOFF) ? b_off[n] : b_mod[n - NOFF];
}

// ---------------- kernel 2b: w_conv split [o][c*9+kk] ----------------
__global__ __launch_bounds__(576) void wcprep_k(const float* __restrict__ w_conv) {
    int idx = blockIdx.x * 576 + threadIdx.x;     // 128 blocks x 576
    float v = w_conv[idx];
    __nv_bfloat16 hi = __float2bfloat16(v);
    __nv_bfloat16 lo = __float2bfloat16(v - __bfloat162float(hi));
    g_wch[idx] = hi;
    g_wcl[idx] = lo;
}

// ---------------- kernel 3: fused bf16x3 GEMM, implicit-conv A (no im2col) ----------------
// D[m][n] = sum_k A[m][k] * w[n][k], k = pos*64 + c.  Chunk = 32 k = (pos, c-half).
// A rows come straight from g_xth/g_xtl shifted by (ki-1)*64 + (kj-1), zfill at borders.
// Stage row layout (128B): chunks 0-3 = hi, 4-7 = lo.
#define BM 128
#define BN 96
#define BK 32
#define NSTAGE 3
#define A_STAGE (BM * 128)               // 16384 B
#define B_STAGE (BN * 128)               // 12288 B
#define STAGE_B (A_STAGE + B_STAGE)      // 28672 B
#define GEMM_SMEM (NSTAGE * STAGE_B)     // 86016 B
#define VCHUNKS 18                       // 9 pos x 2 halves

__device__ __forceinline__ int swz(int r, int c) { return c ^ (r & 7); }

__global__ void __launch_bounds__(256, 2) gemm_mma_k() {
    extern __shared__ char sm[];
    const int tid = threadIdx.x;
    const int wid = tid >> 5;
    const int lane = tid & 31;
    const int warp_m = wid & 3;
    const int warp_n = wid >> 2;
    const int m0 = blockIdx.x * BM;
    const int n0 = blockIdx.y * BN;
    const uint32_t smem_base = smem_u32(sm);

    float acc[2][6][4];
#pragma unroll
    for (int i = 0; i < 2; i++)
#pragma unroll
        for (int j = 0; j < 6; j++)
#pragma unroll
            for (int q = 0; q < 4; q++) acc[i][j][q] = 0.f;

    auto load_stage = [&](int s, int chunk) {
        const int pos = chunk >> 1;
        const int c0v = (chunk & 1) * 32;
        const int ki = pos / 3, kj = pos - ki * 3;
        const int shift = (ki - 1) * 64 + (kj - 1);
        const int k0 = chunk * BK;                    // == pos*64 + c0v
        const uint32_t ab = smem_base + s * STAGE_B;
        const uint32_t bb = ab + A_STAGE;
#pragma unroll
        for (int i = 0; i < 4; i++) {          // A: 1024 16B chunks
            int e = tid + i * 256;
            int r = e >> 3, c = e & 7;
            int mm = m0 + r;
            int wq = mm & 63, hq = (mm >> 6) & 63;
            bool valid = ((unsigned)(wq + kj - 1) < 64u) &&
                         ((unsigned)(hq + ki - 1) < 64u);
            const __nv_bfloat16* base = (c & 4) ? g_xtl : g_xth;
            size_t src = valid ? ((size_t)(mm + shift) * CIN + c0v + (c & 3) * 8) : 0;
            cp_async16_z(ab + r * 128 + swz(r, c) * 16, base + src, valid ? 16u : 0u);
        }
#pragma unroll
        for (int i = 0; i < 3; i++) {          // B: 768 chunks
            int e = tid + i * 256;
            int r = e >> 3, c = e & 7;
            const __nv_bfloat16* src = (c & 4) ? g_wl : g_wh;
            cp_async16(bb + r * 128 + swz(r, c) * 16,
                       src + (size_t)(n0 + r) * KDIM + k0 + (c & 3) * 8);
        }
        asm volatile("cp.async.commit_group;");
    };

    load_stage(0, 0);
    load_stage(1, 1);

    for (int q = 0; q < VCHUNKS; q++) {
        asm volatile("cp.async.wait_group 1;");
        __syncthreads();
        if (q + 2 < VCHUNKS) load_stage((q + 2) % NSTAGE, q + 2);

        const uint32_t ab = smem_base + (q % NSTAGE) * STAGE_B;
        const uint32_t bb = ab + A_STAGE;
#pragma unroll
        for (int ks = 0; ks < 2; ks++) {       // 2 x k16 within BK=32
            uint32_t ah[2][4], al[2][4];
#pragma unroll
            for (int mf = 0; mf < 2; mf++) {
                int r = warp_m * 32 + mf * 16 + (lane & 15);
                int ch = ks * 2 + (lane >> 4);
                ldsm_x4(ah[mf][0], ah[mf][1], ah[mf][2], ah[mf][3],
                        ab + r * 128 + swz(r, ch) * 16);
                ldsm_x4(al[mf][0], al[mf][1], al[mf][2], al[mf][3],
                        ab + r * 128 + swz(r, ch + 4) * 16);
            }
#pragma unroll
            for (int nfp = 0; nfp < 3; nfp++) {
                int r = warp_n * 48 + nfp * 16 + (lane & 7) + ((lane >> 4) & 1) * 8;
                int ch = ks * 2 + ((lane >> 3) & 1);
                uint32_t bh[4], bl[4];
                ldsm_x4(bh[0], bh[1], bh[2], bh[3], bb + r * 128 + swz(r, ch) * 16);
                ldsm_x4(bl[0], bl[1], bl[2], bl[3], bb + r * 128 + swz(r, ch + 4) * 16);
                mma16816(acc[0][2 * nfp],     ah[0], bh);
                mma16816(acc[0][2 * nfp + 1], ah[0], bh + 2);
                mma16816(acc[1][2 * nfp],     ah[1], bh);
                mma16816(acc[1][2 * nfp + 1], ah[1], bh + 2);
                mma16816(acc[0][2 * nfp],     al[0], bh);
                mma16816(acc[0][2 * nfp + 1], al[0], bh + 2);
                mma16816(acc[1][2 * nfp],     al[1], bh);
                mma16816(acc[1][2 * nfp + 1], al[1], bh + 2);
                mma16816(acc[0][2 * nfp],     ah[0], bl);
                mma16816(acc[0][2 * nfp + 1], ah[0], bl + 2);
                mma16816(acc[1][2 * nfp],     ah[1], bl);
                mma16816(acc[1][2 * nfp + 1], ah[1], bl + 2);
            }
        }
    }
    __syncthreads();

    // epilogue: transpose via SMEM, coalesced [n][m] stores
    float* ws = (float*)sm + wid * (48 * 33);
#pragma unroll
    for (int mf = 0; mf < 2; mf++)
#pragma unroll
        for (int nf = 0; nf < 6; nf++)
#pragma unroll
            for (int j = 0; j < 4; j++) {
                int nl = (nf >> 1) * 16 + (nf & 1) * 8 + (lane & 3) * 2 + (j & 1);
                int ml = mf * 16 + ((j >> 1) & 1) * 8 + (lane >> 2);
                ws[nl * 33 + ml] = acc[mf][nf][j];
            }
    __syncwarp();
    {
        const int m = m0 + warp_m * 32 + lane;
#pragma unroll 4
        for (int row = 0; row < 48; row++) {
            int n = n0 + warp_n * 48 + row;
            float v = ws[row * 33 + lane] + g_bias[n];
            if (n < NOFF) {
                v = fminf(MAXOFF, fmaxf(-MAXOFF, v));
                g_off[(size_t)n * MTOT + m] = v;
            } else {
                g_mask[(size_t)(n - NOFF) * MTOT + m] = v;
            }
        }
    }
}

// ---------------- kernel 4: FUSED sampler + output GEMM ----------------
// out[o][m] = sum_j w_conv[o][j] * samp[j][m], samp computed in-kernel (j = c*9+kk).
#define FA_STAGE 16384                    // 128 rows x 128B
#define FA_RING  (3 * FA_STAGE)           // 49152
#define FB_STAGE 16384                    // Bh 8192 + Bl 8192
#define FB_RING  (3 * FB_STAGE)           // 49152
#define FUSED_SMEM (FA_RING + FB_RING)    // 98304

__global__ void __launch_bounds__(256, 2) fused_out_k(const float* __restrict__ x,
                                                      float* __restrict__ out) {
    extern __shared__ char sm[];
    const int tid = threadIdx.x;
    const int wid = tid >> 5;
    const int lane = tid & 31;
    const int warp_o = wid & 1;       // 2 warps x 64 o
    const int warp_n = wid >> 1;      // 4 warps x 32 m
    const int mm0 = blockIdx.x * 128;
    const uint32_t smem_base = smem_u32(sm);

    float acc[4][4][4];
#pragma unroll
    for (int i = 0; i < 4; i++)
#pragma unroll
        for (int j = 0; j < 4; j++)
#pragma unroll
            for (int q = 0; q < 4; q++) acc[i][j][q] = 0.f;

    auto loadA = [&](int chunk) {
        const int k0 = chunk * 32;
        const uint32_t ab = smem_base + (chunk % 3) * FA_STAGE;
#pragma unroll
        for (int i = 0; i < 4; i++) {
            int e = tid + i * 256;
            int r = e >> 3, c = e & 7;
            const __nv_bfloat16* src = (c & 4) ? g_wcl : g_wch;
            cp_async16(ab + r * 128 + swz(r, c) * 16,
                       src + (size_t)r * KDIM + k0 + (c & 3) * 8);
        }
        asm volatile("cp.async.commit_group;");
    };

    const int m2 = (tid & 63) * 2;
    const int msmp = mm0 + m2;
    const int wpix = msmp & 63, hpix = (msmp >> 6) & 63, bpix = msmp >> 12;
    const float* xb = x + ((size_t)bpix * CIN << 12);

    auto computeB = [&](int chunk) {
        const int jbase = chunk * 32;
        const uint32_t bbase = smem_base + FA_RING + (chunk % 3) * FB_STAGE;
#pragma unroll
        for (int i = 0; i < 8; i++) {
            const int jl = (tid >> 6) + 4 * i;        // 0..31
            const int j = jbase + jl;
            const int c = j / 9, kk = j - c * 9;
            const int ki = kk / 3, kj = kk - ki * 3;
            const float* offp  = g_off + ((size_t)(c * 18 + kk * 2)) * MTOT + msmp;
            const float* offp2 = offp + MTOT;
            const float* mp    = g_mask + ((size_t)(c * 9 + kk)) * MTOT + msmp;
            const float* xp    = xb + ((size_t)c << 12);
            float s[2];
#pragma unroll
            for (int t = 0; t < 2; t++) {
                float dy = offp[t], dx = offp2[t], mv = mp[t];
                float py = dy + (float)(hpix + ki - 1);
                float px = dx + (float)(wpix + kj - 1 + t);
                float v = 0.f;
                if (py > -1.f && py < 64.f && px > -1.f && px < 64.f) {
                    float y0f = floorf(py), x0f = floorf(px);
                    float wy = py - y0f, wx = px - x0f;
                    int y0 = (int)y0f, x0 = (int)x0f;
                    float v00 = 0.f, v01 = 0.f, v10 = 0.f, v11 = 0.f;
                    bool yi0 = (unsigned)y0 < 64u;
                    bool yi1 = (unsigned)(y0 + 1) < 64u;
                    bool xi0 = (unsigned)x0 < 64u;
                    bool xi1 = (unsigned)(x0 + 1) < 64u;
                    if (yi0 && xi0) v00 = xp[(y0 << 6) + x0];
                    if (yi0 && xi1) v01 = xp[(y0 << 6) + x0 + 1];
                    if (yi1 && xi0) v10 = xp[((y0 + 1) << 6) + x0];
                    if (yi1 && xi1) v11 = xp[((y0 + 1) << 6) + x0 + 1];
                    v = (1.f - wy) * ((1.f - wx) * v00 + wx * v01) +
                        wy * ((1.f - wx) * v10 + wx * v11);
                }
                s[t] = v * mv;
            }
            __nv_bfloat16 h0 = __float2bfloat16(s[0]);
            __nv_bfloat16 h1 = __float2bfloat16(s[1]);
            __nv_bfloat16 l0 = __float2bfloat16(s[0] - __bfloat162float(h0));
            __nv_bfloat16 l1 = __float2bfloat16(s[1] - __bfloat162float(h1));
            uint32_t hp = (uint32_t)__bfloat16_as_ushort(h0) |
                          ((uint32_t)__bfloat16_as_ushort(h1) << 16);
            uint32_t lp = (uint32_t)__bfloat16_as_ushort(l0) |
                          ((uint32_t)__bfloat16_as_ushort(l1) << 16);
            uint32_t byteoff = (uint32_t)m2 * 2;
            uint32_t addr = bbase + jl * 256 +
                            ((((byteoff >> 4) ^ (jl & 15))) << 4) + (byteoff & 15);
            sts32(addr, hp);
            sts32(addr + 8192, lp);
        }
    };

    loadA(0);
    loadA(1);
    computeB(0);

    for (int q = 0; q < 18; q++) {
        asm volatile("cp.async.wait_group 1;");
        if (q + 1 < 18) computeB(q + 1);
        __syncthreads();
        if (q + 2 < 18) loadA(q + 2);

        const uint32_t ab = smem_base + (q % 3) * FA_STAGE;
        const uint32_t bhb = smem_base + FA_RING + (q % 3) * FB_STAGE;
        const uint32_t blb = bhb + 8192;
#pragma unroll
        for (int ks = 0; ks < 2; ks++) {
            uint32_t ah[4][4], al[4][4];
#pragma unroll
            for (int mf = 0; mf < 4; mf++) {
                int r = warp_o * 64 + mf * 16 + (lane & 15);
                int ch = ks * 2 + (lane >> 4);
                ldsm_x4(ah[mf][0], ah[mf][1], ah[mf][2], ah[mf][3],
                        ab + r * 128 + swz(r, ch) * 16);
                ldsm_x4(al[mf][0], al[mf][1], al[mf][2], al[mf][3],
                        ab + r * 128 + swz(r, ch + 4) * 16);
            }
#pragma unroll
            for (int np = 0; np < 2; np++) {
                int j = ks * 16 + (lane & 15);
                int cn = warp_n * 4 + np * 2 + (lane >> 4);
                uint32_t bh[4], bl[4];
                ldsm_x4t(bh[0], bh[1], bh[2], bh[3],
                         bhb + j * 256 + ((cn ^ (j & 15)) << 4));
                ldsm_x4t(bl[0], bl[1], bl[2], bl[3],
                         blb + j * 256 + ((cn ^ (j & 15)) << 4));
#pragma unroll
                for (int mf = 0; mf < 4; mf++) {
                    mma16816(acc[mf][np * 2],     ah[mf], bh);
                    mma16816(acc[mf][np * 2 + 1], ah[mf], bh + 2);
                    mma16816(acc[mf][np * 2],     al[mf], bh);
                    mma16816(acc[mf][np * 2 + 1], al[mf], bh + 2);
                    mma16816(acc[mf][np * 2],     ah[mf], bl);
                    mma16816(acc[mf][np * 2 + 1], ah[mf], bl + 2);
                }
            }
        }
    }

    // epilogue: direct stores, out[b][o][h][w]
    const int bidx = mm0 >> 12;
    const int rem0 = mm0 & 4095;
#pragma unroll
    for (int mf = 0; mf < 4; mf++) {
#pragma unroll
        for (int nf = 0; nf < 4; nf++) {
            int o = warp_o * 64 + mf * 16 + (lane >> 2);
            int mc = rem0 + warp_n * 32 + nf * 8 + (lane & 3) * 2;
            float* p0 = out + ((size_t)(bidx * OO + o) << 12) + mc;
            p0[0] = acc[mf][nf][0];
            p0[1] = acc[mf][nf][1];
            float* p1 = p0 + (8 << 12);
            p1[0] = acc[mf][nf][2];
            p1[1] = acc[mf][nf][3];
        }
    }
}

// ---------------- launch ----------------
extern "C" void kernel_launch(void* const* d_in, const int* in_sizes, int n_in,
                              void* d_out, int out_size) {
    const float* x      = (const float*)d_in[0];
    const float* w_off  = (const float*)d_in[1];
    const float* b_off  = (const float*)d_in[2];
    const float* w_mod  = (const float*)d_in[3];
    const float* b_mod  = (const float*)d_in[4];
    const float* w_conv = (const float*)d_in[5];
    float* out = (float*)d_out;

    static int smem_set = 0;
    if (!smem_set) {
        cudaFuncSetAttribute(gemm_mma_k, cudaFuncAttributeMaxDynamicSharedMemorySize, GEMM_SMEM);
        cudaFuncSetAttribute(fused_out_k, cudaFuncAttributeMaxDynamicSharedMemorySize, FUSED_SMEM);
        smem_set = 1;
    }

    xt_prep_k<<<MTOT / 64, 256>>>(x);
    wprep_k<<<NTOT, 576>>>(w_off, b_off, w_mod, b_mod);
    wcprep_k<<<OO, 576>>>(w_conv);
    gemm_mma_k<<<dim3(MTOT / BM, NTOT / BN), 256, GEMM_SMEM>>>();
    fused_out_k<<<MTOT / 128, 256, FUSED_SMEM>>>(x, out);
}